// round 15
// baseline (speedup 1.0000x reference)
#include <cuda_runtime.h>
#include <cuda_bf16.h>

// Problem constants (fixed by the reference)
#define NND   100000      // nodes
#define NED   50000       // hyperedges
#define NNZE  1280000     // incidence nnz
#define FT    128
#define HID   64
#define NCLS  32
#define NGR   256

#define XSTR  68          // padded shared stride, activations (floats)
#define WT    72          // padded stride, transposed bf16 weights [n][k]
#define NB_N  1563        // ceil(NND/64)
#define NB_E  782         // ceil(NED/64)

// ---------------- device scratch (static; no allocation allowed) -------------
__device__ float g_x   [NND * HID];
__device__ float g_x0  [NND * HID];
__device__ float g_esum[NED * HID];
__device__ int   g_ecnt[NED];
__device__ float g_y   [NED * HID];
__device__ float g_cls [NND * NCLS];
__device__ int   g_noff[NND + 1];
__device__ int   g_goff[NGR + 1];

// ---------------- bf16 3-pass mma helpers --------------------------------------
__device__ __forceinline__ void mma16(float d[4], const unsigned a[4],
                                      unsigned b0, unsigned b1) {
    asm volatile(
        "mma.sync.aligned.m16n8k16.row.col.f32.bf16.bf16.f32 "
        "{%0,%1,%2,%3}, {%4,%5,%6,%7}, {%8,%9}, {%0,%1,%2,%3};"
        : "+f"(d[0]), "+f"(d[1]), "+f"(d[2]), "+f"(d[3])
        : "r"(a[0]), "r"(a[1]), "r"(a[2]), "r"(a[3]), "r"(b0), "r"(b1));
}

// split a float2 from shared into packed bf16x2 hi + bf16x2 lo
__device__ __forceinline__ void splitA2(const float* __restrict__ p,
                                        unsigned& hi, unsigned& lo) {
    const float2 v = *reinterpret_cast<const float2*>(p);
    __nv_bfloat162 h = __float22bfloat162_rn(v);
    const float2 hf = __bfloat1622float2(h);
    __nv_bfloat162 l = __float22bfloat162_rn(make_float2(v.x - hf.x, v.y - hf.y));
    hi = *reinterpret_cast<unsigned*>(&h);
    lo = *reinterpret_cast<unsigned*>(&l);
}

// warp-level GEMM, bf16 3-pass; B fragments via ldmatrix on transposed weights.
// WhT[n*WT + k] : bf16 hi;  WlT[n*WT + k] : bf16 lo residual
template <int NBLK>
__device__ __forceinline__ void mma_gemm_lm(const float* __restrict__ xs,
                                            const __nv_bfloat16* __restrict__ WhT,
                                            const __nv_bfloat16* __restrict__ WlT,
                                            float d[NBLK][4],
                                            int rbase, int cbase, int lane) {
    const int g    = lane >> 2;
    const int tg   = lane & 3;
    const int lrow = lane & 7;
    const int lsel = (lane >> 3) & 1;
    const unsigned whb = (unsigned)__cvta_generic_to_shared(WhT);
    const unsigned wlb = (unsigned)__cvta_generic_to_shared(WlT);
    #pragma unroll
    for (int kc = 0; kc < 4; kc++) {
        const int k0 = kc * 16;
        const float* ar = xs + (rbase + g) * XSTR + k0;
        unsigned ah[4], al[4];
        splitA2(ar + 2 * tg,            ah[0], al[0]);   // row g,   k 2tg..
        splitA2(ar + 8 * XSTR + 2 * tg, ah[1], al[1]);   // row g+8
        splitA2(ar + 2 * tg + 8,            ah[2], al[2]); // row g,   k 2tg+8..
        splitA2(ar + 8 * XSTR + 2 * tg + 8, ah[3], al[3]); // row g+8
        #pragma unroll
        for (int nb = 0; nb < NBLK; nb++) {
            const int nrow = cbase + nb * 8 + lrow;
            const int koff = k0 + 8 * lsel;
            unsigned bh0, bh1, bl0, bl1;
            const unsigned ha = whb + (unsigned)(nrow * WT + koff) * 2u;
            asm volatile("ldmatrix.sync.aligned.m8n8.x2.shared.b16 {%0,%1}, [%2];"
                         : "=r"(bh0), "=r"(bh1) : "r"(ha));
            const unsigned la = wlb + (unsigned)(nrow * WT + koff) * 2u;
            asm volatile("ldmatrix.sync.aligned.m8n8.x2.shared.b16 {%0,%1}, [%2];"
                         : "=r"(bl0), "=r"(bl1) : "r"(la));
            mma16(d[nb], ah, bh0, bh1);
            mma16(d[nb], ah, bl0, bl1);
            mma16(d[nb], al, bh0, bh1);
        }
    }
}

// ---------------- helpers ------------------------------------------------------
__device__ __forceinline__ int lower_bound_i(const int* __restrict__ a, int n, int key) {
    int lo = 0, hi = n;
    while (lo < hi) {
        int mid = (lo + hi) >> 1;
        if (a[mid] < key) lo = mid + 1; else hi = mid;
    }
    return lo;
}

__global__ void k_node_off(const int* __restrict__ src) {
    int v = blockIdx.x * blockDim.x + threadIdx.x;
    if (v <= NND) g_noff[v] = lower_bound_i(src, NNZE, v);
}

__global__ void k_graph_off(const int* __restrict__ batch) {
    int g = threadIdx.x;
    if (g <= NGR) g_goff[g] = lower_bound_i(batch, NND, g);
}

// zero edge accumulators (esum + ecnt) — runs before each layer's scatter
__global__ void k_zero_e() {
    const int tot = NED * HID;
    for (int i = blockIdx.x * blockDim.x + threadIdx.x; i < tot;
         i += gridDim.x * blockDim.x) {
        g_esum[i] = 0.f;
        if (i < NED) g_ecnt[i] = 0;
    }
}

// load a 64-row x 64-col tile (row-major, stride 64) into padded shared
__device__ __forceinline__ void load_tile64(float* __restrict__ xs,
                                            const float* __restrict__ g,
                                            int row0, int nrows, int t) {
    #pragma unroll
    for (int i = t; i < 64 * 16; i += 256) {
        int r  = i >> 4;
        int c4 = (i & 15) * 4;
        float4 v = make_float4(0.f, 0.f, 0.f, 0.f);
        int row = row0 + r;
        if (row < nrows) v = *reinterpret_cast<const float4*>(&g[(size_t)row * 64 + c4]);
        *reinterpret_cast<float4*>(&xs[r * XSTR + c4]) = v;
    }
}

// split a k-row-major weight block into TRANSPOSED bf16 hi/lo shared layouts
template <int KK, int NC>
__device__ __forceinline__ void load_wsplit_T(__nv_bfloat16* __restrict__ WhT,
                                              __nv_bfloat16* __restrict__ WlT,
                                              const float* __restrict__ W, int t) {
    for (int i = t; i < KK * NC; i += 256) {
        const int k = i / NC, n = i % NC;
        const float w = W[i];
        const __nv_bfloat16 h = __float2bfloat16(w);
        WhT[n * WT + k] = h;
        WlT[n * WT + k] = __float2bfloat16(w - __bfloat162float(h));
    }
}

// h-MLP on in-shared tile + fused V->E scatter (shared device routine)
__device__ __forceinline__ void h_and_scatter(
    float* __restrict__ xs, __nv_bfloat16* __restrict__ Wh, __nv_bfloat16* __restrict__ Wl,
    const float* __restrict__ Wa, const float* __restrict__ bas,
    const float* __restrict__ Wb, const float* __restrict__ bbs,
    const int* __restrict__ src, const int* __restrict__ dst,
    int row0, int t, int rbase, int cbase, int lane)
{
    const int g = lane >> 2, tg = lane & 3;
    load_wsplit_T<64, 64>(Wh, Wl, Wa, t);
    __syncthreads();

    float d1[4][4];
    #pragma unroll
    for (int nb = 0; nb < 4; nb++)
        #pragma unroll
        for (int c = 0; c < 4; c++) d1[nb][c] = 0.f;
    mma_gemm_lm<4>(xs, Wh, Wl, d1, rbase, cbase, lane);
    __syncthreads();

    {
        const int rl = rbase + g, rh = rl + 8;
        #pragma unroll
        for (int nb = 0; nb < 4; nb++) {
            const int c = cbase + nb * 8 + tg * 2;
            xs[rl * XSTR + c]     = fmaxf(d1[nb][0] + bas[c], 0.f);
            xs[rl * XSTR + c + 1] = fmaxf(d1[nb][1] + bas[c + 1], 0.f);
            xs[rh * XSTR + c]     = fmaxf(d1[nb][2] + bas[c], 0.f);
            xs[rh * XSTR + c + 1] = fmaxf(d1[nb][3] + bas[c + 1], 0.f);
        }
    }
    load_wsplit_T<64, 64>(Wh, Wl, Wb, t);
    __syncthreads();

    float d2[4][4];
    #pragma unroll
    for (int nb = 0; nb < 4; nb++)
        #pragma unroll
        for (int c = 0; c < 4; c++) d2[nb][c] = 0.f;
    mma_gemm_lm<4>(xs, Wh, Wl, d2, rbase, cbase, lane);
    __syncthreads();                 // all xs reads done -> overwrite with h

    {
        const int rl = rbase + g, rh = rl + 8;
        #pragma unroll
        for (int nb = 0; nb < 4; nb++) {
            const int c = cbase + nb * 8 + tg * 2;
            xs[rl * XSTR + c]     = d2[nb][0] + bbs[c];
            xs[rl * XSTR + c + 1] = d2[nb][1] + bbs[c + 1];
            xs[rh * XSTR + c]     = d2[nb][2] + bbs[c];
            xs[rh * XSTR + c + 1] = d2[nb][3] + bbs[c + 1];
        }
    }
    __syncthreads();

    // fused scatter: incidences with src in [row0, row0+64)
    const int jbeg = g_noff[row0];
    const int jend = g_noff[min(row0 + 64, NND)];
    const int work = (jend - jbeg) * 16;
    const int q4 = (t & 15) * 4;
    for (int idx = t; idx < work; idx += 256) {
        const int j = jbeg + (idx >> 4);
        const int s = __ldg(&src[j]) - row0;
        const int dd = __ldg(&dst[j]);
        const float4 v = *reinterpret_cast<const float4*>(&xs[s * XSTR + q4]);
        float* p = &g_esum[(size_t)dd * 64 + q4];
        asm volatile("red.global.add.v4.f32 [%0], {%1,%2,%3,%4};"
                     :: "l"(p), "f"(v.x), "f"(v.y), "f"(v.z), "f"(v.w) : "memory");
        if ((t & 15) == 0) atomicAdd(&g_ecnt[dd], 1);
    }
}

// combine stage on a tile (xs holds x on entry; Wh/Wl scratch; result frags in out)
struct CombineOut { float d2[4][4]; };
__device__ __forceinline__ void combine_tile(
    float* __restrict__ xs, __nv_bfloat16* __restrict__ Wh, __nv_bfloat16* __restrict__ Wl,
    const float* __restrict__ W2, const float* __restrict__ b2s,
    const float* __restrict__ W3, float* __restrict__ cinv,
    const int* __restrict__ offs, const int* __restrict__ dst,
    int row0, int t, int tx, int ty, int rbase, int cbase, int lane,
    CombineOut& out)
{
    const int g = lane >> 2, tg = lane & 3;
    load_wsplit_T<64, 64>(Wh, Wl, W2, t);     // W2a
    __syncthreads();

    float d[4][4];
    #pragma unroll
    for (int nb = 0; nb < 4; nb++)
        #pragma unroll
        for (int c = 0; c < 4; c++) d[nb][c] = 0.f;
    mma_gemm_lm<4>(xs, Wh, Wl, d, rbase, cbase, lane);   // x @ W2a

    // scalar gather into registers
    float z[4][4];
    #pragma unroll
    for (int r = 0; r < 4; r++)
        #pragma unroll
        for (int c = 0; c < 4; c++) z[r][c] = 0.f;
    #pragma unroll
    for (int r = 0; r < 4; r++) {
        const int lr = ty * 4 + r;
        const int v = row0 + lr;
        if (v < NND) {
            const int beg = offs[lr], end = offs[lr + 1];
            for (int j = beg; j < end; j++) {
                const int dd = __ldg(&dst[j]);
                const float4 yv = *reinterpret_cast<const float4*>(&g_y[(size_t)dd * 64 + tx * 4]);
                z[r][0] += yv.x; z[r][1] += yv.y; z[r][2] += yv.z; z[r][3] += yv.w;
            }
        }
    }
    __syncthreads();   // GEMM1 xs reads done everywhere -> reuse xs as z staging

    #pragma unroll
    for (int r = 0; r < 4; r++) {
        const int lr = ty * 4 + r;
        *reinterpret_cast<float4*>(&xs[lr * XSTR + tx * 4]) =
            make_float4(z[r][0], z[r][1], z[r][2], z[r][3]);
    }
    load_wsplit_T<64, 64>(Wh, Wl, W3, t);    // overlap W3 load with staging
    if (t < 64) {
        int cnt = offs[t + 1] - offs[t];
        cinv[t] = (cnt > 0) ? 1.f / (float)cnt : 0.f;
    }
    __syncthreads();

    // compose u into xs at fragment positions (read z, overwrite with u)
    {
        const int rl = rbase + g, rh = rl + 8;
        const int grl = row0 + rl, grh = row0 + rh;
        const float il = cinv[rl], ih = cinv[rh];
        #pragma unroll
        for (int nb = 0; nb < 4; nb++) {
            const int c = cbase + nb * 8 + tg * 2;
            float2 x0l = make_float2(0.f, 0.f), x0h = make_float2(0.f, 0.f);
            if (grl < NND) x0l = *reinterpret_cast<const float2*>(&g_x0[(size_t)grl * 64 + c]);
            if (grh < NND) x0h = *reinterpret_cast<const float2*>(&g_x0[(size_t)grh * 64 + c]);
            float zl0 = xs[rl * XSTR + c], zl1 = xs[rl * XSTR + c + 1];
            float zh0 = xs[rh * XSTR + c], zh1 = xs[rh * XSTR + c + 1];
            float xv0 = (il > 0.f) ? d[nb][0] + b2s[c]     + zl0 * il : 0.f;
            float xv1 = (il > 0.f) ? d[nb][1] + b2s[c + 1] + zl1 * il : 0.f;
            float xv2 = (ih > 0.f) ? d[nb][2] + b2s[c]     + zh0 * ih : 0.f;
            float xv3 = (ih > 0.f) ? d[nb][3] + b2s[c + 1] + zh1 * ih : 0.f;
            xs[rl * XSTR + c]     = 0.5f * xv0 + 0.5f * x0l.x;
            xs[rl * XSTR + c + 1] = 0.5f * xv1 + 0.5f * x0l.y;
            xs[rh * XSTR + c]     = 0.5f * xv2 + 0.5f * x0h.x;
            xs[rh * XSTR + c + 1] = 0.5f * xv3 + 0.5f * x0h.y;
        }
    }
    __syncthreads();

    #pragma unroll
    for (int nb = 0; nb < 4; nb++)
        #pragma unroll
        for (int c = 0; c < 4; c++) out.d2[nb][c] = 0.f;
    mma_gemm_lm<4>(xs, Wh, Wl, out.d2, rbase, cbase, lane);
    __syncthreads();   // xs reads done; caller may overwrite xs
}

// ---------------- fused: input layer + h-MLP + scatter ------------------------
__global__ void __launch_bounds__(256, 4) k_in_h(const float* __restrict__ X,
                                                 const float* __restrict__ W,
                                                 const float* __restrict__ b,
                                                 const float* __restrict__ Wa,
                                                 const float* __restrict__ ba,
                                                 const float* __restrict__ Wb,
                                                 const float* __restrict__ bb,
                                                 const int* __restrict__ src,
                                                 const int* __restrict__ dst) {
    __shared__ __align__(16) __nv_bfloat16 Wh[64 * WT];
    __shared__ __align__(16) __nv_bfloat16 Wl[64 * WT];
    __shared__ __align__(16) float xs[64 * XSTR];
    __shared__ float bs[64], bas[64], bbs[64];
    const int t = threadIdx.y * 16 + threadIdx.x;
    const int wid = t >> 5, lane = t & 31;
    const int rbase = (wid & 3) * 16, cbase = (wid >> 2) * 32;
    const int g = lane >> 2, tg = lane & 3;
    const int row0 = blockIdx.x * 64;
    if (t < 64) { bs[t] = b[t]; bas[t] = ba[t]; bbs[t] = bb[t]; }

    float d[4][4];
    #pragma unroll
    for (int nb = 0; nb < 4; nb++)
        #pragma unroll
        for (int c = 0; c < 4; c++) d[nb][c] = 0.f;

    for (int ch = 0; ch < 2; ch++) {
        __syncthreads();
        load_wsplit_T<64, 64>(Wh, Wl, W + ch * 64 * 64, t);
        #pragma unroll
        for (int i = t; i < 64 * 16; i += 256) {
            int r = i >> 4, c4 = (i & 15) * 4;
            float4 v = make_float4(0.f, 0.f, 0.f, 0.f);
            int row = row0 + r;
            if (row < NND) v = *reinterpret_cast<const float4*>(&X[(size_t)row * FT + ch * 64 + c4]);
            *reinterpret_cast<float4*>(&xs[r * XSTR + c4]) = v;
        }
        __syncthreads();
        mma_gemm_lm<4>(xs, Wh, Wl, d, rbase, cbase, lane);
    }
    __syncthreads();   // final mma's xs reads done

    // x = relu(d + b): store to g_x/g_x0 AND keep in xs fragments
    const int rlo = row0 + rbase + g;
    const int rhi = rlo + 8;
    {
        const int rl = rbase + g, rh = rl + 8;
        #pragma unroll
        for (int nb = 0; nb < 4; nb++) {
            const int c = cbase + nb * 8 + tg * 2;
            float o0 = fmaxf(d[nb][0] + bs[c], 0.f);
            float o1 = fmaxf(d[nb][1] + bs[c + 1], 0.f);
            float o2 = fmaxf(d[nb][2] + bs[c], 0.f);
            float o3 = fmaxf(d[nb][3] + bs[c + 1], 0.f);
            xs[rl * XSTR + c] = o0;  xs[rl * XSTR + c + 1] = o1;
            xs[rh * XSTR + c] = o2;  xs[rh * XSTR + c + 1] = o3;
            if (rlo < NND) {
                float2 o = make_float2(o0, o1);
                *reinterpret_cast<float2*>(&g_x [(size_t)rlo * 64 + c]) = o;
                *reinterpret_cast<float2*>(&g_x0[(size_t)rlo * 64 + c]) = o;
            }
            if (rhi < NND) {
                float2 o = make_float2(o2, o3);
                *reinterpret_cast<float2*>(&g_x [(size_t)rhi * 64 + c]) = o;
                *reinterpret_cast<float2*>(&g_x0[(size_t)rhi * 64 + c]) = o;
            }
        }
    }
    h_and_scatter(xs, Wh, Wl, Wa, bas, Wb, bbs, src, dst, row0, t, rbase, cbase, lane);
}

// ---------------- Y = (esum / max(cnt,1)) @ W2b -------------------------------
__global__ void __launch_bounds__(256, 4) k_y(const float* __restrict__ W2) {
    __shared__ __align__(16) __nv_bfloat16 Wh[64 * WT];
    __shared__ __align__(16) __nv_bfloat16 Wl[64 * WT];
    __shared__ __align__(16) float xs[64 * XSTR];
    __shared__ float cs[64];
    const int t = threadIdx.y * 16 + threadIdx.x;
    const int wid = t >> 5, lane = t & 31;
    const int rbase = (wid & 3) * 16, cbase = (wid >> 2) * 32;
    const int g = lane >> 2, tg = lane & 3;
    const int row0 = blockIdx.x * 64;
    load_wsplit_T<64, 64>(Wh, Wl, W2 + 64 * 64, t);   // W2b
    if (t < 64) {
        int row = row0 + t;
        int c = (row < NED) ? g_ecnt[row] : 1;
        cs[t] = 1.f / fmaxf((float)c, 1.f);
    }
    load_tile64(xs, g_esum, row0, NED, t);
    __syncthreads();

    #pragma unroll
    for (int i = t; i < 64 * 16; i += 256) {
        int r = i >> 4, c4 = (i & 15) * 4;
        float inv = cs[r];
        float4 v = *reinterpret_cast<float4*>(&xs[r * XSTR + c4]);
        v.x *= inv; v.y *= inv; v.z *= inv; v.w *= inv;
        *reinterpret_cast<float4*>(&xs[r * XSTR + c4]) = v;
    }
    __syncthreads();

    float d[4][4];
    #pragma unroll
    for (int nb = 0; nb < 4; nb++)
        #pragma unroll
        for (int c = 0; c < 4; c++) d[nb][c] = 0.f;
    mma_gemm_lm<4>(xs, Wh, Wl, d, rbase, cbase, lane);

    const int rlo = row0 + rbase + g;
    const int rhi = rlo + 8;
    #pragma unroll
    for (int nb = 0; nb < 4; nb++) {
        const int c = cbase + nb * 8 + tg * 2;
        if (rlo < NED)
            *reinterpret_cast<float2*>(&g_y[(size_t)rlo * 64 + c]) =
                make_float2(d[nb][0], d[nb][1]);
        if (rhi < NED)
            *reinterpret_cast<float2*>(&g_y[(size_t)rhi * 64 + c]) =
                make_float2(d[nb][2], d[nb][3]);
    }
}

// ---------------- fused: combine(L) + h-MLP(L+1) + scatter --------------------
__global__ void __launch_bounds__(256, 4) k_combine_h(const float* __restrict__ W2,
                                                      const float* __restrict__ b2,
                                                      const float* __restrict__ W3,
                                                      const float* __restrict__ b3,
                                                      const float* __restrict__ Wa,
                                                      const float* __restrict__ ba,
                                                      const float* __restrict__ Wb,
                                                      const float* __restrict__ bb,
                                                      const int* __restrict__ dst,
                                                      const int* __restrict__ src) {
    __shared__ __align__(16) __nv_bfloat16 Wh[64 * WT];
    __shared__ __align__(16) __nv_bfloat16 Wl[64 * WT];
    __shared__ __align__(16) float xs[64 * XSTR];
    __shared__ float b2s[64], b3s[64], bas[64], bbs[64], cinv[64];
    __shared__ int offs[65];
    const int tx = threadIdx.x, ty = threadIdx.y;
    const int t = ty * 16 + tx;
    const int wid = t >> 5, lane = t & 31;
    const int rbase = (wid & 3) * 16, cbase = (wid >> 2) * 32;
    const int g = lane >> 2, tg = lane & 3;
    const int row0 = blockIdx.x * 64;
    if (t < 64) { b2s[t] = b2[t]; b3s[t] = b3[t]; bas[t] = ba[t]; bbs[t] = bb[t]; }
    if (t < 65) offs[t] = g_noff[min(row0 + t, NND)];
    load_tile64(xs, g_x, row0, NND, t);

    CombineOut co;
    combine_tile(xs, Wh, Wl, W2, b2s, W3, cinv, offs, dst,
                 row0, t, tx, ty, rbase, cbase, lane, co);

    // x_new = relu(d2 + b3): store to g_x (needed by next combine) AND keep in xs
    const int rlo = row0 + rbase + g;
    const int rhi = rlo + 8;
    {
        const int rl = rbase + g, rh = rl + 8;
        #pragma unroll
        for (int nb = 0; nb < 4; nb++) {
            const int c = cbase + nb * 8 + tg * 2;
            float o0 = fmaxf(co.d2[nb][0] + b3s[c], 0.f);
            float o1 = fmaxf(co.d2[nb][1] + b3s[c + 1], 0.f);
            float o2 = fmaxf(co.d2[nb][2] + b3s[c], 0.f);
            float o3 = fmaxf(co.d2[nb][3] + b3s[c + 1], 0.f);
            xs[rl * XSTR + c] = o0;  xs[rl * XSTR + c + 1] = o1;
            xs[rh * XSTR + c] = o2;  xs[rh * XSTR + c + 1] = o3;
            if (rlo < NND)
                *reinterpret_cast<float2*>(&g_x[(size_t)rlo * 64 + c]) = make_float2(o0, o1);
            if (rhi < NND)
                *reinterpret_cast<float2*>(&g_x[(size_t)rhi * 64 + c]) = make_float2(o2, o3);
        }
    }
    h_and_scatter(xs, Wh, Wl, Wa, bas, Wb, bbs, src, dst, row0, t, rbase, cbase, lane);
}

// ---------------- fused: combine(last) + classifier ---------------------------
__global__ void __launch_bounds__(256, 4) k_combine_cls(const float* __restrict__ W2,
                                                        const float* __restrict__ b2,
                                                        const float* __restrict__ W3,
                                                        const float* __restrict__ b3,
                                                        const float* __restrict__ Wc1,
                                                        const float* __restrict__ bc1,
                                                        const float* __restrict__ Wc2,
                                                        const float* __restrict__ bc2,
                                                        const int* __restrict__ dst) {
    __shared__ __align__(16) __nv_bfloat16 Wh[64 * WT];
    __shared__ __align__(16) __nv_bfloat16 Wl[64 * WT];
    __shared__ __align__(16) float xs[64 * XSTR];
    __shared__ float b2s[64], b3s[64], b1s[64], bcs[32], cinv[64];
    __shared__ int offs[65];
    const int tx = threadIdx.x, ty = threadIdx.y;
    const int t = ty * 16 + tx;
    const int wid = t >> 5, lane = t & 31;
    const int rbase = (wid & 3) * 16, cbase = (wid >> 2) * 32;
    const int g = lane >> 2, tg = lane & 3;
    const int row0 = blockIdx.x * 64;
    if (t < 64) { b2s[t] = b2[t]; b3s[t] = b3[t]; b1s[t] = bc1[t]; }
    if (t < 32) bcs[t] = bc2[t];
    if (t < 65) offs[t] = g_noff[min(row0 + t, NND)];
    load_tile64(xs, g_x, row0, NND, t);

    CombineOut co;
    combine_tile(xs, Wh, Wl, W2, b2s, W3, cinv, offs, dst,
                 row0, t, tx, ty, rbase, cbase, lane, co);

    // x_new = relu(d2 + b3) kept ONLY in xs
    {
        const int rl = rbase + g, rh = rl + 8;
        #pragma unroll
        for (int nb = 0; nb < 4; nb++) {
            const int c = cbase + nb * 8 + tg * 2;
            xs[rl * XSTR + c]     = fmaxf(co.d2[nb][0] + b3s[c], 0.f);
            xs[rl * XSTR + c + 1] = fmaxf(co.d2[nb][1] + b3s[c + 1], 0.f);
            xs[rh * XSTR + c]     = fmaxf(co.d2[nb][2] + b3s[c], 0.f);
            xs[rh * XSTR + c + 1] = fmaxf(co.d2[nb][3] + b3s[c + 1], 0.f);
        }
    }
    load_wsplit_T<64, 64>(Wh, Wl, Wc1, t);
    __syncthreads();

    float d1[4][4];
    #pragma unroll
    for (int nb = 0; nb < 4; nb++)
        #pragma unroll
        for (int c = 0; c < 4; c++) d1[nb][c] = 0.f;
    mma_gemm_lm<4>(xs, Wh, Wl, d1, rbase, cbase, lane);
    __syncthreads();

    {
        const int rl = rbase + g, rh = rl + 8;
        #pragma unroll
        for (int nb = 0; nb < 4; nb++) {
            const int c = cbase + nb * 8 + tg * 2;
            xs[rl * XSTR + c]     = fmaxf(d1[nb][0] + b1s[c], 0.f);
            xs[rl * XSTR + c + 1] = fmaxf(d1[nb][1] + b1s[c + 1], 0.f);
            xs[rh * XSTR + c]     = fmaxf(d1[nb][2] + b1s[c], 0.f);
            xs[rh * XSTR + c + 1] = fmaxf(d1[nb][3] + b1s[c + 1], 0.f);
        }
    }
    load_wsplit_T<64, 32>(Wh, Wl, Wc2, t);   // 64x32 classifier head, transposed
    __syncthreads();

    const int cbase2 = (wid >> 2) * 16;
    float d2[2][4];
    #pragma unroll
    for (int nb = 0; nb < 2; nb++)
        #pragma unroll
        for (int c = 0; c < 4; c++) d2[nb][c] = 0.f;
    mma_gemm_lm<2>(xs, Wh, Wl, d2, rbase, cbase2, lane);

    const int rlo = row0 + rbase + g;
    const int rhi = rlo + 8;
    #pragma unroll
    for (int nb = 0; nb < 2; nb++) {
        const int c = cbase2 + nb * 8 + tg * 2;
        if (rlo < NND)
            *reinterpret_cast<float2*>(&g_cls[(size_t)rlo * 32 + c]) =
                make_float2(d2[nb][0] + bcs[c], d2[nb][1] + bcs[c + 1]);
        if (rhi < NND)
            *reinterpret_cast<float2*>(&g_cls[(size_t)rhi * 32 + c]) =
                make_float2(d2[nb][2] + bcs[c], d2[nb][3] + bcs[c + 1]);
    }
}

// ---------------- readout: per-graph mean over sorted all_batch ---------------
__global__ void k_readout(float* __restrict__ out) {
    __shared__ float part[8][NCLS];
    const int g = blockIdx.x;
    const int tx = threadIdx.x, ty = threadIdx.y;  // (32, 8)
    const int beg = g_goff[g], end = g_goff[g + 1];
    float s = 0.f;
    for (int j = beg + ty; j < end; j += 8)
        s += g_cls[(size_t)j * NCLS + tx];
    part[ty][tx] = s;
    __syncthreads();
    if (ty == 0) {
        float tot = 0.f;
        #pragma unroll
        for (int r = 0; r < 8; r++) tot += part[r][tx];
        const int c = end - beg;
        out[g * NCLS + tx] = tot / fmaxf((float)c, 1.f);
    }
}

// ---------------- launch ------------------------------------------------------
extern "C" void kernel_launch(void* const* d_in, const int* in_sizes, int n_in,
                              void* d_out, int out_size) {
    const float* X       = (const float*)d_in[0];
    const int*   v2e_src = (const int*)  d_in[1];
    const int*   v2e_dst = (const int*)  d_in[2];
    const int*   batch   = (const int*)  d_in[3];
    const float* W_in    = (const float*)d_in[4];
    const float* b_in    = (const float*)d_in[5];
    const float* W1a     = (const float*)d_in[6];
    const float* b1a     = (const float*)d_in[7];
    const float* W1b     = (const float*)d_in[8];
    const float* b1b     = (const float*)d_in[9];
    const float* W2      = (const float*)d_in[10];
    const float* b2      = (const float*)d_in[11];
    const float* W3      = (const float*)d_in[12];
    const float* b3      = (const float*)d_in[13];
    const float* Wc1     = (const float*)d_in[14];
    const float* bc1     = (const float*)d_in[15];
    const float* Wc2     = (const float*)d_in[16];
    const float* bc2     = (const float*)d_in[17];
    float* out = (float*)d_out;

    const dim3 blk(16, 16);

    k_node_off<<<(NND + 1 + 255) / 256, 256>>>(v2e_src);
    k_graph_off<<<1, NGR + 1>>>(batch);

    k_zero_e<<<2048, 256>>>();
    k_in_h<<<NB_N, blk>>>(X, W_in, b_in, W1a, b1a, W1b, b1b, v2e_src, v2e_dst);
    k_y<<<NB_E, blk>>>(W2);

    k_zero_e<<<2048, 256>>>();
    k_combine_h<<<NB_N, blk>>>(W2, b2, W3, b3, W1a, b1a, W1b, b1b, v2e_dst, v2e_src);
    k_y<<<NB_E, blk>>>(W2);

    k_combine_cls<<<NB_N, blk>>>(W2, b2, W3, b3, Wc1, bc1, Wc2, bc2, v2e_dst);
    k_readout<<<NGR, dim3(32, 8)>>>(out);
}

// round 16
// speedup vs baseline: 1.0451x; 1.0451x over previous
#include <cuda_runtime.h>
#include <cuda_bf16.h>

// Problem constants (fixed by the reference)
#define NND   100000      // nodes
#define NED   50000       // hyperedges
#define NNZE  1280000     // incidence nnz
#define FT    128
#define HID   64
#define NCLS  32
#define NGR   256

#define XSTR  68          // padded shared stride, activations (floats)
#define WSTR  68          // padded stride, transposed hi weights [n][k] (floats)
#define WLTS  72          // padded stride, transposed lo weights [n][kperm] (bf16)
#define NB_N  1563        // ceil(NND/64)
#define NB_E  782         // ceil(NED/64)

// ---------------- device scratch (static; no allocation allowed) -------------
__device__ float g_x   [NND * HID];
__device__ float g_x0  [NND * HID];
__device__ float g_esum[NED * HID];
__device__ int   g_ecnt[NED];
__device__ float g_y   [NED * HID];
__device__ float g_cls [NND * NCLS];
__device__ int   g_noff[NND + 1];
__device__ int   g_goff[NGR + 1];

// ---------------- tf32 mma helpers --------------------------------------------
__device__ __forceinline__ unsigned to_tf32(float f) {
    unsigned r;
    asm("cvt.rna.tf32.f32 %0, %1;" : "=r"(r) : "f"(f));
    return r;
}
__device__ __forceinline__ void split_tf32(float f, unsigned& hi, unsigned& lo) {
    hi = to_tf32(f);
    lo = to_tf32(f - __uint_as_float(hi));
}
__device__ __forceinline__ void mma8(float d[4],
                                     unsigned a0, unsigned a1, unsigned a2, unsigned a3,
                                     unsigned b0, unsigned b1) {
    asm volatile(
        "mma.sync.aligned.m16n8k8.row.col.f32.tf32.tf32.f32 "
        "{%0,%1,%2,%3}, {%4,%5,%6,%7}, {%8,%9}, {%0,%1,%2,%3};"
        : "+f"(d[0]), "+f"(d[1]), "+f"(d[2]), "+f"(d[3])
        : "r"(a0), "r"(a1), "r"(a2), "r"(a3), "r"(b0), "r"(b1));
}

// warp-level GEMM; B fragments come from ldmatrix on TRANSPOSED pre-split weights.
// WhT[n*WSTR + k]  : tf32-valued fp32 hi part (row = n, col = k)
// WlT[n*WLTS + kp] : bf16 lo residual, k-permuted so (k=tg, k=tg+4) are adjacent
template <int NBLK>
__device__ __forceinline__ void mma_gemm_lm(const float* __restrict__ xs,
                                            const float* __restrict__ WhT,
                                            const __nv_bfloat16* __restrict__ WlT,
                                            float d[NBLK][4],
                                            int rbase, int cbase, int lane) {
    const int g  = lane >> 2;
    const int tg = lane & 3;
    const int lrow = lane & 7;
    const int lmat = (lane >> 3) & 1;
    const unsigned whb = (unsigned)__cvta_generic_to_shared(WhT);
    const unsigned wlb = (unsigned)__cvta_generic_to_shared(WlT);
    #pragma unroll
    for (int ko = 0; ko < 8; ko++) {
        const int k0 = ko * 8;
        const float* ar = xs + (rbase + g) * XSTR + k0;
        unsigned ah[4], al[4];
        split_tf32(ar[tg],                ah[0], al[0]);
        split_tf32(ar[8 * XSTR + tg],     ah[1], al[1]);
        split_tf32(ar[tg + 4],            ah[2], al[2]);
        split_tf32(ar[8 * XSTR + tg + 4], ah[3], al[3]);
        #pragma unroll
        for (int nb = 0; nb < NBLK; nb++) {
            const int nbase = cbase + nb * 8;
            unsigned bh0, bh1;
            const unsigned haddr = whb + (((nbase + lrow) * WSTR) + k0 + 4 * lmat) * 4u;
            asm volatile("ldmatrix.sync.aligned.m8n8.x2.shared.b16 {%0,%1}, [%2];"
                         : "=r"(bh0), "=r"(bh1) : "r"(haddr));
            unsigned blp;
            const unsigned laddr = wlb + ((nbase + lrow) * WLTS) * 2u + k0 * 2u;
            asm volatile("ldmatrix.sync.aligned.m8n8.x1.shared.b16 {%0}, [%1];"
                         : "=r"(blp) : "r"(laddr));
            const float2 wl = __bfloat1622float2(
                *reinterpret_cast<const __nv_bfloat162*>(&blp));
            const unsigned bl0 = __float_as_uint(wl.x);
            const unsigned bl1 = __float_as_uint(wl.y);
            mma8(d[nb], ah[0], ah[1], ah[2], ah[3], bh0, bh1);
            mma8(d[nb], ah[0], ah[1], ah[2], ah[3], bl0, bl1);
            mma8(d[nb], al[0], al[1], al[2], al[3], bh0, bh1);
        }
    }
}

// ---------------- helpers ------------------------------------------------------
__device__ __forceinline__ int lower_bound_i(const int* __restrict__ a, int n, int key) {
    int lo = 0, hi = n;
    while (lo < hi) {
        int mid = (lo + hi) >> 1;
        if (a[mid] < key) lo = mid + 1; else hi = mid;
    }
    return lo;
}

__global__ void k_node_off(const int* __restrict__ src) {
    int v = blockIdx.x * blockDim.x + threadIdx.x;
    if (v <= NND) g_noff[v] = lower_bound_i(src, NNZE, v);
}

__global__ void k_graph_off(const int* __restrict__ batch) {
    int g = threadIdx.x;
    if (g <= NGR) g_goff[g] = lower_bound_i(batch, NND, g);
}

// zero edge accumulators (esum + ecnt) — runs before each layer's scatter
__global__ void k_zero_e() {
    const int tot = NED * HID;
    for (int i = blockIdx.x * blockDim.x + threadIdx.x; i < tot;
         i += gridDim.x * blockDim.x) {
        g_esum[i] = 0.f;
        if (i < NED) g_ecnt[i] = 0;
    }
}

// load a 64-row x 64-col tile (row-major, stride 64) into padded shared
__device__ __forceinline__ void load_tile64(float* __restrict__ xs,
                                            const float* __restrict__ g,
                                            int row0, int nrows, int t) {
    #pragma unroll
    for (int i = t; i < 64 * 16; i += 256) {
        int r  = i >> 4;
        int c4 = (i & 15) * 4;
        float4 v = make_float4(0.f, 0.f, 0.f, 0.f);
        int row = row0 + r;
        if (row < nrows) v = *reinterpret_cast<const float4*>(&g[(size_t)row * 64 + c4]);
        *reinterpret_cast<float4*>(&xs[r * XSTR + c4]) = v;
    }
}

// split a KN-row-major weight block into TRANSPOSED hi/lo shared layouts
template <int KK, int NC>
__device__ __forceinline__ void load_wsplit_T(float* __restrict__ WhT,
                                              __nv_bfloat16* __restrict__ WlT,
                                              const float* __restrict__ W, int t) {
    for (int i = t; i < KK * NC; i += 256) {
        const int k = i / NC, n = i % NC;
        const float w = W[i];
        const float fh = __uint_as_float(to_tf32(w));
        WhT[n * WSTR + k] = fh;
        const int ko = k >> 3, j = k & 7;
        const int col = ko * 8 + ((j < 4) ? (2 * j) : (2 * (j - 4) + 1));
        WlT[n * WLTS + col] = __float2bfloat16(w - fh);
    }
}

// h-MLP on in-shared tile + fused V->E scatter via bulk async reduce
__device__ __forceinline__ void h_and_scatter(
    float* __restrict__ xs, float* __restrict__ Wh, __nv_bfloat16* __restrict__ Wl,
    const float* __restrict__ Wa, const float* __restrict__ bas,
    const float* __restrict__ Wb, const float* __restrict__ bbs,
    const int* __restrict__ src, const int* __restrict__ dst,
    int row0, int t, int rbase, int cbase, int lane)
{
    const int g = lane >> 2, tg = lane & 3;
    load_wsplit_T<64, 64>(Wh, Wl, Wa, t);
    __syncthreads();

    float d1[4][4];
    #pragma unroll
    for (int nb = 0; nb < 4; nb++)
        #pragma unroll
        for (int c = 0; c < 4; c++) d1[nb][c] = 0.f;
    mma_gemm_lm<4>(xs, Wh, Wl, d1, rbase, cbase, lane);
    __syncthreads();

    {
        const int rl = rbase + g, rh = rl + 8;
        #pragma unroll
        for (int nb = 0; nb < 4; nb++) {
            const int c = cbase + nb * 8 + tg * 2;
            xs[rl * XSTR + c]     = fmaxf(d1[nb][0] + bas[c], 0.f);
            xs[rl * XSTR + c + 1] = fmaxf(d1[nb][1] + bas[c + 1], 0.f);
            xs[rh * XSTR + c]     = fmaxf(d1[nb][2] + bas[c], 0.f);
            xs[rh * XSTR + c + 1] = fmaxf(d1[nb][3] + bas[c + 1], 0.f);
        }
    }
    load_wsplit_T<64, 64>(Wh, Wl, Wb, t);
    __syncthreads();

    float d2[4][4];
    #pragma unroll
    for (int nb = 0; nb < 4; nb++)
        #pragma unroll
        for (int c = 0; c < 4; c++) d2[nb][c] = 0.f;
    mma_gemm_lm<4>(xs, Wh, Wl, d2, rbase, cbase, lane);
    __syncthreads();                 // all xs reads done -> overwrite with h

    {
        const int rl = rbase + g, rh = rl + 8;
        #pragma unroll
        for (int nb = 0; nb < 4; nb++) {
            const int c = cbase + nb * 8 + tg * 2;
            xs[rl * XSTR + c]     = d2[nb][0] + bbs[c];
            xs[rl * XSTR + c + 1] = d2[nb][1] + bbs[c + 1];
            xs[rh * XSTR + c]     = d2[nb][2] + bbs[c];
            xs[rh * XSTR + c + 1] = d2[nb][3] + bbs[c + 1];
        }
    }
    __syncthreads();

    // fused scatter: incidences with src in [row0, row0+64).
    // One 256-byte bulk async reduce (shared -> global, L2-side add) per incidence.
    const int jbeg = g_noff[row0];
    const int jend = g_noff[min(row0 + 64, NND)];
    for (int j = jbeg + t; j < jend; j += 256) {
        const int s = __ldg(&src[j]) - row0;
        const int dd = __ldg(&dst[j]);
        const unsigned saddr = (unsigned)__cvta_generic_to_shared(&xs[s * XSTR]);
        asm volatile(
            "cp.reduce.async.bulk.global.shared::cta.bulk_group.add.f32 [%0], [%1], 256;"
            :: "l"(&g_esum[(size_t)dd * 64]), "r"(saddr) : "memory");
        atomicAdd(&g_ecnt[dd], 1);
    }
    asm volatile("cp.async.bulk.commit_group;" ::: "memory");
    asm volatile("cp.async.bulk.wait_group 0;" ::: "memory");
    __syncthreads();   // keep xs alive until every thread's bulk reads completed
}

// combine stage on a tile (xs holds x on entry; Wh/Wl scratch; result frags in out)
struct CombineOut { float d2[4][4]; };
__device__ __forceinline__ void combine_tile(
    float* __restrict__ xs, float* __restrict__ Wh, __nv_bfloat16* __restrict__ Wl,
    const float* __restrict__ W2, const float* __restrict__ b2s,
    const float* __restrict__ W3, float* __restrict__ cinv,
    const int* __restrict__ offs, const int* __restrict__ dst,
    int row0, int t, int tx, int ty, int rbase, int cbase, int lane,
    CombineOut& out)
{
    const int g = lane >> 2, tg = lane & 3;
    load_wsplit_T<64, 64>(Wh, Wl, W2, t);     // W2a
    __syncthreads();

    float d[4][4];
    #pragma unroll
    for (int nb = 0; nb < 4; nb++)
        #pragma unroll
        for (int c = 0; c < 4; c++) d[nb][c] = 0.f;
    mma_gemm_lm<4>(xs, Wh, Wl, d, rbase, cbase, lane);   // x @ W2a

    // scalar gather into registers
    float z[4][4];
    #pragma unroll
    for (int r = 0; r < 4; r++)
        #pragma unroll
        for (int c = 0; c < 4; c++) z[r][c] = 0.f;
    #pragma unroll
    for (int r = 0; r < 4; r++) {
        const int lr = ty * 4 + r;
        const int v = row0 + lr;
        if (v < NND) {
            const int beg = offs[lr], end = offs[lr + 1];
            for (int j = beg; j < end; j++) {
                const int dd = __ldg(&dst[j]);
                const float4 yv = *reinterpret_cast<const float4*>(&g_y[(size_t)dd * 64 + tx * 4]);
                z[r][0] += yv.x; z[r][1] += yv.y; z[r][2] += yv.z; z[r][3] += yv.w;
            }
        }
    }
    __syncthreads();   // MMA reads of Wh/Wl done -> reuse Wh as zs

    float* zs = Wh;
    #pragma unroll
    for (int r = 0; r < 4; r++) {
        const int lr = ty * 4 + r;
        zs[lr * WSTR + tx * 4 + 0] = z[r][0];
        zs[lr * WSTR + tx * 4 + 1] = z[r][1];
        zs[lr * WSTR + tx * 4 + 2] = z[r][2];
        zs[lr * WSTR + tx * 4 + 3] = z[r][3];
    }
    if (t < 64) {
        int cnt = offs[t + 1] - offs[t];
        cinv[t] = (cnt > 0) ? 1.f / (float)cnt : 0.f;
    }
    __syncthreads();

    // compose u into xs at fragment positions
    {
        const int rl = rbase + g, rh = rl + 8;
        const int grl = row0 + rl, grh = row0 + rh;
        const float il = cinv[rl], ih = cinv[rh];
        #pragma unroll
        for (int nb = 0; nb < 4; nb++) {
            const int c = cbase + nb * 8 + tg * 2;
            float2 x0l = make_float2(0.f, 0.f), x0h = make_float2(0.f, 0.f);
            if (grl < NND) x0l = *reinterpret_cast<const float2*>(&g_x0[(size_t)grl * 64 + c]);
            if (grh < NND) x0h = *reinterpret_cast<const float2*>(&g_x0[(size_t)grh * 64 + c]);
            float xv0 = (il > 0.f) ? d[nb][0] + b2s[c]     + zs[rl * WSTR + c]     * il : 0.f;
            float xv1 = (il > 0.f) ? d[nb][1] + b2s[c + 1] + zs[rl * WSTR + c + 1] * il : 0.f;
            float xv2 = (ih > 0.f) ? d[nb][2] + b2s[c]     + zs[rh * WSTR + c]     * ih : 0.f;
            float xv3 = (ih > 0.f) ? d[nb][3] + b2s[c + 1] + zs[rh * WSTR + c + 1] * ih : 0.f;
            xs[rl * XSTR + c]     = 0.5f * xv0 + 0.5f * x0l.x;
            xs[rl * XSTR + c + 1] = 0.5f * xv1 + 0.5f * x0l.y;
            xs[rh * XSTR + c]     = 0.5f * xv2 + 0.5f * x0h.x;
            xs[rh * XSTR + c + 1] = 0.5f * xv3 + 0.5f * x0h.y;
        }
    }
    __syncthreads();   // compose reads of zs done -> reload weights
    load_wsplit_T<64, 64>(Wh, Wl, W3, t);
    __syncthreads();

    #pragma unroll
    for (int nb = 0; nb < 4; nb++)
        #pragma unroll
        for (int c = 0; c < 4; c++) out.d2[nb][c] = 0.f;
    mma_gemm_lm<4>(xs, Wh, Wl, out.d2, rbase, cbase, lane);
    __syncthreads();   // xs reads done; caller may overwrite xs
}

// ---------------- fused: input layer + h-MLP + scatter ------------------------
__global__ void __launch_bounds__(256, 4) k_in_h(const float* __restrict__ X,
                                                 const float* __restrict__ W,
                                                 const float* __restrict__ b,
                                                 const float* __restrict__ Wa,
                                                 const float* __restrict__ ba,
                                                 const float* __restrict__ Wb,
                                                 const float* __restrict__ bb,
                                                 const int* __restrict__ src,
                                                 const int* __restrict__ dst) {
    __shared__ __align__(16) float Wh[64 * WSTR];
    __shared__ __align__(16) __nv_bfloat16 Wl[64 * WLTS];
    __shared__ __align__(16) float xs[64 * XSTR];
    __shared__ float bs[64], bas[64], bbs[64];
    const int t = threadIdx.y * 16 + threadIdx.x;
    const int wid = t >> 5, lane = t & 31;
    const int rbase = (wid & 3) * 16, cbase = (wid >> 2) * 32;
    const int g = lane >> 2, tg = lane & 3;
    const int row0 = blockIdx.x * 64;
    if (t < 64) { bs[t] = b[t]; bas[t] = ba[t]; bbs[t] = bb[t]; }

    float d[4][4];
    #pragma unroll
    for (int nb = 0; nb < 4; nb++)
        #pragma unroll
        for (int c = 0; c < 4; c++) d[nb][c] = 0.f;

    for (int ch = 0; ch < 2; ch++) {
        __syncthreads();
        load_wsplit_T<64, 64>(Wh, Wl, W + ch * 64 * 64, t);
        #pragma unroll
        for (int i = t; i < 64 * 16; i += 256) {
            int r = i >> 4, c4 = (i & 15) * 4;
            float4 v = make_float4(0.f, 0.f, 0.f, 0.f);
            int row = row0 + r;
            if (row < NND) v = *reinterpret_cast<const float4*>(&X[(size_t)row * FT + ch * 64 + c4]);
            *reinterpret_cast<float4*>(&xs[r * XSTR + c4]) = v;
        }
        __syncthreads();
        mma_gemm_lm<4>(xs, Wh, Wl, d, rbase, cbase, lane);
    }
    __syncthreads();   // final mma's xs reads done

    // x = relu(d + b): store to g_x/g_x0 AND keep in xs fragments
    const int rlo = row0 + rbase + g;
    const int rhi = rlo + 8;
    {
        const int rl = rbase + g, rh = rl + 8;
        #pragma unroll
        for (int nb = 0; nb < 4; nb++) {
            const int c = cbase + nb * 8 + tg * 2;
            float o0 = fmaxf(d[nb][0] + bs[c], 0.f);
            float o1 = fmaxf(d[nb][1] + bs[c + 1], 0.f);
            float o2 = fmaxf(d[nb][2] + bs[c], 0.f);
            float o3 = fmaxf(d[nb][3] + bs[c + 1], 0.f);
            xs[rl * XSTR + c] = o0;  xs[rl * XSTR + c + 1] = o1;
            xs[rh * XSTR + c] = o2;  xs[rh * XSTR + c + 1] = o3;
            if (rlo < NND) {
                float2 o = make_float2(o0, o1);
                *reinterpret_cast<float2*>(&g_x [(size_t)rlo * 64 + c]) = o;
                *reinterpret_cast<float2*>(&g_x0[(size_t)rlo * 64 + c]) = o;
            }
            if (rhi < NND) {
                float2 o = make_float2(o2, o3);
                *reinterpret_cast<float2*>(&g_x [(size_t)rhi * 64 + c]) = o;
                *reinterpret_cast<float2*>(&g_x0[(size_t)rhi * 64 + c]) = o;
            }
        }
    }
    h_and_scatter(xs, Wh, Wl, Wa, bas, Wb, bbs, src, dst, row0, t, rbase, cbase, lane);
}

// ---------------- Y = (esum / max(cnt,1)) @ W2b -------------------------------
__global__ void __launch_bounds__(256, 4) k_y(const float* __restrict__ W2) {
    __shared__ __align__(16) float Wh[64 * WSTR];
    __shared__ __align__(16) __nv_bfloat16 Wl[64 * WLTS];
    __shared__ __align__(16) float xs[64 * XSTR];
    __shared__ float cs[64];
    const int t = threadIdx.y * 16 + threadIdx.x;
    const int wid = t >> 5, lane = t & 31;
    const int rbase = (wid & 3) * 16, cbase = (wid >> 2) * 32;
    const int g = lane >> 2, tg = lane & 3;
    const int row0 = blockIdx.x * 64;
    load_wsplit_T<64, 64>(Wh, Wl, W2 + 64 * 64, t);   // W2b
    if (t < 64) {
        int row = row0 + t;
        int c = (row < NED) ? g_ecnt[row] : 1;
        cs[t] = 1.f / fmaxf((float)c, 1.f);
    }
    load_tile64(xs, g_esum, row0, NED, t);
    __syncthreads();

    #pragma unroll
    for (int i = t; i < 64 * 16; i += 256) {
        int r = i >> 4, c4 = (i & 15) * 4;
        float inv = cs[r];
        float4 v = *reinterpret_cast<float4*>(&xs[r * XSTR + c4]);
        v.x *= inv; v.y *= inv; v.z *= inv; v.w *= inv;
        *reinterpret_cast<float4*>(&xs[r * XSTR + c4]) = v;
    }
    __syncthreads();

    float d[4][4];
    #pragma unroll
    for (int nb = 0; nb < 4; nb++)
        #pragma unroll
        for (int c = 0; c < 4; c++) d[nb][c] = 0.f;
    mma_gemm_lm<4>(xs, Wh, Wl, d, rbase, cbase, lane);

    const int rlo = row0 + rbase + g;
    const int rhi = rlo + 8;
    #pragma unroll
    for (int nb = 0; nb < 4; nb++) {
        const int c = cbase + nb * 8 + tg * 2;
        if (rlo < NED)
            *reinterpret_cast<float2*>(&g_y[(size_t)rlo * 64 + c]) =
                make_float2(d[nb][0], d[nb][1]);
        if (rhi < NED)
            *reinterpret_cast<float2*>(&g_y[(size_t)rhi * 64 + c]) =
                make_float2(d[nb][2], d[nb][3]);
    }
}

// ---------------- fused: combine(L) + h-MLP(L+1) + scatter --------------------
__global__ void __launch_bounds__(256, 4) k_combine_h(const float* __restrict__ W2,
                                                      const float* __restrict__ b2,
                                                      const float* __restrict__ W3,
                                                      const float* __restrict__ b3,
                                                      const float* __restrict__ Wa,
                                                      const float* __restrict__ ba,
                                                      const float* __restrict__ Wb,
                                                      const float* __restrict__ bb,
                                                      const int* __restrict__ dst,
                                                      const int* __restrict__ src) {
    __shared__ __align__(16) float Wh[64 * WSTR];
    __shared__ __align__(16) __nv_bfloat16 Wl[64 * WLTS];
    __shared__ __align__(16) float xs[64 * XSTR];
    __shared__ float b2s[64], b3s[64], bas[64], bbs[64], cinv[64];
    __shared__ int offs[65];
    const int tx = threadIdx.x, ty = threadIdx.y;
    const int t = ty * 16 + tx;
    const int wid = t >> 5, lane = t & 31;
    const int rbase = (wid & 3) * 16, cbase = (wid >> 2) * 32;
    const int g = lane >> 2, tg = lane & 3;
    const int row0 = blockIdx.x * 64;
    if (t < 64) { b2s[t] = b2[t]; b3s[t] = b3[t]; bas[t] = ba[t]; bbs[t] = bb[t]; }
    if (t < 65) offs[t] = g_noff[min(row0 + t, NND)];
    load_tile64(xs, g_x, row0, NND, t);

    CombineOut co;
    combine_tile(xs, Wh, Wl, W2, b2s, W3, cinv, offs, dst,
                 row0, t, tx, ty, rbase, cbase, lane, co);

    // x_new = relu(d2 + b3): store to g_x (needed by next combine) AND keep in xs
    const int rlo = row0 + rbase + g;
    const int rhi = rlo + 8;
    {
        const int rl = rbase + g, rh = rl + 8;
        #pragma unroll
        for (int nb = 0; nb < 4; nb++) {
            const int c = cbase + nb * 8 + tg * 2;
            float o0 = fmaxf(co.d2[nb][0] + b3s[c], 0.f);
            float o1 = fmaxf(co.d2[nb][1] + b3s[c + 1], 0.f);
            float o2 = fmaxf(co.d2[nb][2] + b3s[c], 0.f);
            float o3 = fmaxf(co.d2[nb][3] + b3s[c + 1], 0.f);
            xs[rl * XSTR + c] = o0;  xs[rl * XSTR + c + 1] = o1;
            xs[rh * XSTR + c] = o2;  xs[rh * XSTR + c + 1] = o3;
            if (rlo < NND)
                *reinterpret_cast<float2*>(&g_x[(size_t)rlo * 64 + c]) = make_float2(o0, o1);
            if (rhi < NND)
                *reinterpret_cast<float2*>(&g_x[(size_t)rhi * 64 + c]) = make_float2(o2, o3);
        }
    }
    h_and_scatter(xs, Wh, Wl, Wa, bas, Wb, bbs, src, dst, row0, t, rbase, cbase, lane);
}

// ---------------- fused: combine(last) + classifier ---------------------------
__global__ void __launch_bounds__(256, 4) k_combine_cls(const float* __restrict__ W2,
                                                        const float* __restrict__ b2,
                                                        const float* __restrict__ W3,
                                                        const float* __restrict__ b3,
                                                        const float* __restrict__ Wc1,
                                                        const float* __restrict__ bc1,
                                                        const float* __restrict__ Wc2,
                                                        const float* __restrict__ bc2,
                                                        const int* __restrict__ dst) {
    __shared__ __align__(16) float Wh[64 * WSTR];
    __shared__ __align__(16) __nv_bfloat16 Wl[64 * WLTS];
    __shared__ __align__(16) float xs[64 * XSTR];
    __shared__ float b2s[64], b3s[64], b1s[64], bcs[32], cinv[64];
    __shared__ int offs[65];
    const int tx = threadIdx.x, ty = threadIdx.y;
    const int t = ty * 16 + tx;
    const int wid = t >> 5, lane = t & 31;
    const int rbase = (wid & 3) * 16, cbase = (wid >> 2) * 32;
    const int g = lane >> 2, tg = lane & 3;
    const int row0 = blockIdx.x * 64;
    if (t < 64) { b2s[t] = b2[t]; b3s[t] = b3[t]; b1s[t] = bc1[t]; }
    if (t < 32) bcs[t] = bc2[t];
    if (t < 65) offs[t] = g_noff[min(row0 + t, NND)];
    load_tile64(xs, g_x, row0, NND, t);

    CombineOut co;
    combine_tile(xs, Wh, Wl, W2, b2s, W3, cinv, offs, dst,
                 row0, t, tx, ty, rbase, cbase, lane, co);

    // x_new = relu(d2 + b3) kept ONLY in xs
    {
        const int rl = rbase + g, rh = rl + 8;
        #pragma unroll
        for (int nb = 0; nb < 4; nb++) {
            const int c = cbase + nb * 8 + tg * 2;
            xs[rl * XSTR + c]     = fmaxf(co.d2[nb][0] + b3s[c], 0.f);
            xs[rl * XSTR + c + 1] = fmaxf(co.d2[nb][1] + b3s[c + 1], 0.f);
            xs[rh * XSTR + c]     = fmaxf(co.d2[nb][2] + b3s[c], 0.f);
            xs[rh * XSTR + c + 1] = fmaxf(co.d2[nb][3] + b3s[c + 1], 0.f);
        }
    }
    load_wsplit_T<64, 64>(Wh, Wl, Wc1, t);
    __syncthreads();

    float d1[4][4];
    #pragma unroll
    for (int nb = 0; nb < 4; nb++)
        #pragma unroll
        for (int c = 0; c < 4; c++) d1[nb][c] = 0.f;
    mma_gemm_lm<4>(xs, Wh, Wl, d1, rbase, cbase, lane);
    __syncthreads();

    {
        const int rl = rbase + g, rh = rl + 8;
        #pragma unroll
        for (int nb = 0; nb < 4; nb++) {
            const int c = cbase + nb * 8 + tg * 2;
            xs[rl * XSTR + c]     = fmaxf(d1[nb][0] + b1s[c], 0.f);
            xs[rl * XSTR + c + 1] = fmaxf(d1[nb][1] + b1s[c + 1], 0.f);
            xs[rh * XSTR + c]     = fmaxf(d1[nb][2] + b1s[c], 0.f);
            xs[rh * XSTR + c + 1] = fmaxf(d1[nb][3] + b1s[c + 1], 0.f);
        }
    }
    load_wsplit_T<64, 32>(Wh, Wl, Wc2, t);   // 64x32 classifier head, transposed
    __syncthreads();

    const int cbase2 = (wid >> 2) * 16;
    float d2[2][4];
    #pragma unroll
    for (int nb = 0; nb < 2; nb++)
        #pragma unroll
        for (int c = 0; c < 4; c++) d2[nb][c] = 0.f;
    mma_gemm_lm<2>(xs, Wh, Wl, d2, rbase, cbase2, lane);

    const int rlo = row0 + rbase + g;
    const int rhi = rlo + 8;
    #pragma unroll
    for (int nb = 0; nb < 2; nb++) {
        const int c = cbase2 + nb * 8 + tg * 2;
        if (rlo < NND)
            *reinterpret_cast<float2*>(&g_cls[(size_t)rlo * 32 + c]) =
                make_float2(d2[nb][0] + bcs[c], d2[nb][1] + bcs[c + 1]);
        if (rhi < NND)
            *reinterpret_cast<float2*>(&g_cls[(size_t)rhi * 32 + c]) =
                make_float2(d2[nb][2] + bcs[c], d2[nb][3] + bcs[c + 1]);
    }
}

// ---------------- readout: per-graph mean over sorted all_batch ---------------
__global__ void k_readout(float* __restrict__ out) {
    __shared__ float part[8][NCLS];
    const int g = blockIdx.x;
    const int tx = threadIdx.x, ty = threadIdx.y;  // (32, 8)
    const int beg = g_goff[g], end = g_goff[g + 1];
    float s = 0.f;
    for (int j = beg + ty; j < end; j += 8)
        s += g_cls[(size_t)j * NCLS + tx];
    part[ty][tx] = s;
    __syncthreads();
    if (ty == 0) {
        float tot = 0.f;
        #pragma unroll
        for (int r = 0; r < 8; r++) tot += part[r][tx];
        const int c = end - beg;
        out[g * NCLS + tx] = tot / fmaxf((float)c, 1.f);
    }
}

// ---------------- launch ------------------------------------------------------
extern "C" void kernel_launch(void* const* d_in, const int* in_sizes, int n_in,
                              void* d_out, int out_size) {
    const float* X       = (const float*)d_in[0];
    const int*   v2e_src = (const int*)  d_in[1];
    const int*   v2e_dst = (const int*)  d_in[2];
    const int*   batch   = (const int*)  d_in[3];
    const float* W_in    = (const float*)d_in[4];
    const float* b_in    = (const float*)d_in[5];
    const float* W1a     = (const float*)d_in[6];
    const float* b1a     = (const float*)d_in[7];
    const float* W1b     = (const float*)d_in[8];
    const float* b1b     = (const float*)d_in[9];
    const float* W2      = (const float*)d_in[10];
    const float* b2      = (const float*)d_in[11];
    const float* W3      = (const float*)d_in[12];
    const float* b3      = (const float*)d_in[13];
    const float* Wc1     = (const float*)d_in[14];
    const float* bc1     = (const float*)d_in[15];
    const float* Wc2     = (const float*)d_in[16];
    const float* bc2     = (const float*)d_in[17];
    float* out = (float*)d_out;

    const dim3 blk(16, 16);

    k_node_off<<<(NND + 1 + 255) / 256, 256>>>(v2e_src);
    k_graph_off<<<1, NGR + 1>>>(batch);

    k_zero_e<<<2048, 256>>>();
    k_in_h<<<NB_N, blk>>>(X, W_in, b_in, W1a, b1a, W1b, b1b, v2e_src, v2e_dst);
    k_y<<<NB_E, blk>>>(W2);

    k_zero_e<<<2048, 256>>>();
    k_combine_h<<<NB_N, blk>>>(W2, b2, W3, b3, W1a, b1a, W1b, b1b, v2e_dst, v2e_src);
    k_y<<<NB_E, blk>>>(W2);

    k_combine_cls<<<NB_N, blk>>>(W2, b2, W3, b3, Wc1, bc1, Wc2, bc2, v2e_dst);
    k_readout<<<NGR, dim3(32, 8)>>>(out);
}